// round 8
// baseline (speedup 1.0000x reference)
#include <cuda_runtime.h>
#include <cstdint>

#define B_ 4
#define S_ 2048
#define E_ 1024
#define H_ 16
#define D_ 64
#define MTOT (B_*S_)   // 8192

// Scratch (device globals: allocation-free rule)
__device__ float g_Q[B_*S_*E_];
__device__ float g_K[B_*S_*E_];
__device__ float g_V[B_*S_*E_];
__device__ float g_Ctx[B_*S_*E_];

// ---------------------------------------------------------------------------
// helpers
// ---------------------------------------------------------------------------
// HMMA.TF32 reads the top 19 bits of an fp32 register. +0x1000 on the bit
// pattern = round-to-nearest (ties away) in 1 IADD. (== cvt.rna numerics.)
__device__ __forceinline__ uint32_t rtf(float x) {
    return __float_as_uint(x) + 0x1000u;
}

__device__ __forceinline__ void mma_tf32(float* c, const uint32_t* a,
                                         uint32_t b0, uint32_t b1) {
    asm volatile(
        "mma.sync.aligned.m16n8k8.row.col.f32.tf32.tf32.f32 "
        "{%0,%1,%2,%3}, {%4,%5,%6,%7}, {%8,%9}, {%0,%1,%2,%3};"
        : "+f"(c[0]), "+f"(c[1]), "+f"(c[2]), "+f"(c[3])
        : "r"(a[0]), "r"(a[1]), "r"(a[2]), "r"(a[3]), "r"(b0), "r"(b1));
}

__device__ __forceinline__ void cp_async16(uint32_t saddr, const void* g) {
    asm volatile("cp.async.cg.shared.global [%0], [%1], 16;"
                 :: "r"(saddr), "l"(g));
}
__device__ __forceinline__ void cp_commit() {
    asm volatile("cp.async.commit_group;");
}
template <int N>
__device__ __forceinline__ void cp_wait() {
    asm volatile("cp.async.wait_group %0;" :: "n"(N));
}

// ---------------------------------------------------------------------------
// tf32 GEMM (NT): C[m,n] = sum_k A[m,k]*B[n,k] (+ bias[n])
// CTA 128x128, BK=16, 512 thr (16 warps, 4x4 grid), warp tile 32x32.
// ~80 regs/thread -> 16 warps/SM = 4 warps/SMSP (2x the old 64x32 version).
// 3-stage cp.async pipeline, one __syncthreads per k-tile.
// RN rounding at fragment load (+0x1000). smem pitch 20: conflict-free.
// ---------------------------------------------------------------------------
#define GP 20
#define GSTG (128 * GP)
#define GEMM_SMEM_FLOATS (6 * GSTG)   // As[3] + Bs[3] = 61440 B

__global__ __launch_bounds__(512, 1) void gemm_tf32_nt(
    const float* __restrict__ A, const float* __restrict__ Bm,
    const float* __restrict__ bias, float* __restrict__ C,
    int M, int N, int K)
{
    extern __shared__ float smg[];
    float* As = smg;             // 3 buffers of GSTG
    float* Bs = smg + 3 * GSTG;

    const int tid = threadIdx.x;
    const int warp = tid >> 5, lane = tid & 31;
    const int g = lane >> 2, q = lane & 3;
    const int wm = warp >> 2;          // 0..3 (32-row slabs)
    const int wn = warp & 3;           // 0..3 (32-col slabs)
    const int bm = blockIdx.y, bn = blockIdx.x;

    // staging: 512 thr, one 16B chunk of A and one of B per tile each
    const int lrow = tid >> 2;             // 0..127
    const int lcol = (tid & 3) * 4;        // 0,4,8,12
    const float* Ap = A + (size_t)(bm * 128 + lrow) * K + lcol;
    const float* Bp = Bm + (size_t)(bn * 128 + lrow) * K + lcol;

    uint32_t sA0 = (uint32_t)__cvta_generic_to_shared(&As[lrow * GP + lcol]);
    uint32_t sB0 = (uint32_t)__cvta_generic_to_shared(&Bs[lrow * GP + lcol]);
    const uint32_t stg = (uint32_t)(GSTG * sizeof(float));

    float acc[2][4][4];
#pragma unroll
    for (int i = 0; i < 2; i++)
#pragma unroll
        for (int j = 0; j < 4; j++)
#pragma unroll
            for (int t = 0; t < 4; t++) acc[i][j][t] = 0.f;

    const int nt = K / 16;
    // prologue: stage tiles 0 and 1 into bufs 0 and 1
#pragma unroll
    for (int p = 0; p < 2; p++) {
        cp_async16(sA0 + p * stg, Ap + p * 16);
        cp_async16(sB0 + p * stg, Bp + p * 16);
        cp_commit();
    }

    for (int kt = 0; kt < nt; kt++) {
        const int cur = kt % 3;
        cp_wait<1>();          // tile kt resident
        __syncthreads();       // also: readers of buf (kt+2)%3 (from kt-1) done
        if (kt + 2 < nt) {
            const int nxt = (kt + 2) % 3;
            cp_async16(sA0 + nxt * stg, Ap + (kt + 2) * 16);
            cp_async16(sB0 + nxt * stg, Bp + (kt + 2) * 16);
            cp_commit();
        } else {
            cp_commit();       // empty group keeps count in step for cp_wait<1>
        }

        const float* as = As + cur * GSTG;
        const float* bs = Bs + cur * GSTG;
#pragma unroll
        for (int kh = 0; kh < 2; kh++) {
            const int k0 = kh * 8;
            uint32_t af[2][4];
#pragma unroll
            for (int i = 0; i < 2; i++) {
                int r = wm * 32 + i * 16 + g;
                af[i][0] = rtf(as[r * GP + k0 + q]);
                af[i][1] = rtf(as[(r + 8) * GP + k0 + q]);
                af[i][2] = rtf(as[r * GP + k0 + q + 4]);
                af[i][3] = rtf(as[(r + 8) * GP + k0 + q + 4]);
            }
#pragma unroll
            for (int j = 0; j < 4; j++) {
                int n = wn * 32 + j * 8 + g;
                uint32_t bf0 = rtf(bs[n * GP + k0 + q]);
                uint32_t bf1 = rtf(bs[n * GP + k0 + q + 4]);
#pragma unroll
                for (int i = 0; i < 2; i++)
                    mma_tf32(acc[i][j], af[i], bf0, bf1);
            }
        }
    }

    // epilogue
#pragma unroll
    for (int i = 0; i < 2; i++) {
        int r0 = bm * 128 + wm * 32 + i * 16 + g;
#pragma unroll
        for (int j = 0; j < 4; j++) {
            int col = bn * 128 + wn * 32 + j * 8 + 2 * q;
            float bx = 0.f, by = 0.f;
            if (bias) { bx = bias[col]; by = bias[col + 1]; }
            float2 v0 = make_float2(acc[i][j][0] + bx, acc[i][j][1] + by);
            float2 v1 = make_float2(acc[i][j][2] + bx, acc[i][j][3] + by);
            *(float2*)&C[(size_t)r0 * N + col] = v0;
            *(float2*)&C[(size_t)(r0 + 8) * N + col] = v1;
        }
    }
}

// ---------------------------------------------------------------------------
// tf32 flash attention. BQ=128, BKV=64, 256 threads (8 warps).
// Warp w owns q-rows [w*16, w*16+16) (m16). Same smem as the m32 version
// (105472 B -> 2 CTA/SM) but 2x the warps -> 16 warps/SM (4/SMSP).
// __launch_bounds__(256,2) pins regs <=128 so 2 CTAs actually fit.
// RN rounding at smem staging. Pitches: Qs/Ks/Ps 68, Vs 72 (conflict-free).
// ---------------------------------------------------------------------------
#define QP 68
#define VP 72
#define FLASH_SMEM_FLOATS (128*QP + 64*QP + 64*VP + 128*QP)   // 26368

__global__ __launch_bounds__(256, 2) void flash_tf32_kernel(
    const float* __restrict__ Q, const float* __restrict__ K,
    const float* __restrict__ V, float* __restrict__ O)
{
    extern __shared__ float sm[];
    float* Qs = sm;                    // [128][QP]
    float* Ks = Qs + 128 * QP;         // [64][QP]
    float* Vs = Ks + 64 * QP;          // [64][VP]
    float* Ps = Vs + 64 * VP;          // [128][QP]

    const int tid = threadIdx.x;
    const int warp = tid >> 5, lane = tid & 31;
    const int g = lane >> 2, q = lane & 3;
    const int b = blockIdx.z, h = blockIdx.y;
    const int q0 = blockIdx.x * 128;
    const int base = b * S_ * E_ + h * D_;
    const int r = warp * 16 + g;       // this warp's q-row pair base

    // Stage Q tile [128 q][64 d], scaled by 1/8 (exact) + RN bias.
    // 8192 floats = 8 iters x 256 thr x float4.
#pragma unroll
    for (int t = 0; t < 8; t++) {
        int u = tid + t * 256;
        int rr = u >> 4, cc = (u & 15) * 4;
        float4 v = *(const float4*)&Q[base + (size_t)(q0 + rr) * E_ + cc];
        uint4 o;
        o.x = rtf(v.x * 0.125f); o.y = rtf(v.y * 0.125f);
        o.z = rtf(v.z * 0.125f); o.w = rtf(v.w * 0.125f);
        *(uint4*)&Qs[rr * QP + cc] = o;
    }

    float m0 = -1e30f, m1 = -1e30f, l0 = 0.f, l1 = 0.f;
    float oacc[8][4];
#pragma unroll
    for (int j = 0; j < 8; j++)
#pragma unroll
        for (int t = 0; t < 4; t++) oacc[j][t] = 0.f;

    for (int t0 = 0; t0 < S_; t0 += 64) {
        __syncthreads();   // prior-iter Ks/Vs readers done; also covers Qs init
        // K/V tiles 64x64 = 4096 floats; 4 iters x 256 thr x float4.
#pragma unroll
        for (int t = 0; t < 4; t++) {
            int u = tid + t * 256;
            int rr = u >> 4, cc = (u & 15) * 4;
            float4 kv = *(const float4*)&K[base + (size_t)(t0 + rr) * E_ + cc];
            float4 vv = *(const float4*)&V[base + (size_t)(t0 + rr) * E_ + cc];
            uint4 ko, vo;
            ko.x = rtf(kv.x); ko.y = rtf(kv.y); ko.z = rtf(kv.z); ko.w = rtf(kv.w);
            vo.x = rtf(vv.x); vo.y = rtf(vv.y); vo.z = rtf(vv.z); vo.w = rtf(vv.w);
            *(uint4*)&Ks[rr * QP + cc] = ko;
            *(uint4*)&Vs[rr * VP + cc] = vo;
        }
        __syncthreads();

        // ---- S = Q @ K^T  (m16 x n64, k=64) ----
        float sacc[8][4];
#pragma unroll
        for (int j = 0; j < 8; j++)
#pragma unroll
            for (int t = 0; t < 4; t++) sacc[j][t] = 0.f;

#pragma unroll
        for (int ks = 0; ks < 8; ks++) {
            int k0 = ks * 8;
            uint32_t a[4];
            a[0] = __float_as_uint(Qs[r * QP + k0 + q]);
            a[1] = __float_as_uint(Qs[(r + 8) * QP + k0 + q]);
            a[2] = __float_as_uint(Qs[r * QP + k0 + q + 4]);
            a[3] = __float_as_uint(Qs[(r + 8) * QP + k0 + q + 4]);
#pragma unroll
            for (int j = 0; j < 8; j++) {
                int n = j * 8 + g;
                uint32_t b0 = __float_as_uint(Ks[n * QP + k0 + q]);
                uint32_t b1 = __float_as_uint(Ks[n * QP + k0 + q + 4]);
                mma_tf32(sacc[j], a, b0, b1);
            }
        }

        // ---- online softmax (rows r and r+8; reduce across 4 lanes) ----
        float mx0 = -1e30f, mx1 = -1e30f;
#pragma unroll
        for (int j = 0; j < 8; j++) {
            mx0 = fmaxf(mx0, fmaxf(sacc[j][0], sacc[j][1]));
            mx1 = fmaxf(mx1, fmaxf(sacc[j][2], sacc[j][3]));
        }
        mx0 = fmaxf(mx0, __shfl_xor_sync(0xffffffffu, mx0, 1));
        mx0 = fmaxf(mx0, __shfl_xor_sync(0xffffffffu, mx0, 2));
        mx1 = fmaxf(mx1, __shfl_xor_sync(0xffffffffu, mx1, 1));
        mx1 = fmaxf(mx1, __shfl_xor_sync(0xffffffffu, mx1, 2));
        float nm0 = fmaxf(m0, mx0), nm1 = fmaxf(m1, mx1);
        float al0 = __expf(m0 - nm0), al1 = __expf(m1 - nm1);
        m0 = nm0; m1 = nm1;

        float rs0 = 0.f, rs1 = 0.f;
#pragma unroll
        for (int j = 0; j < 8; j++) {
            float p0 = __expf(sacc[j][0] - nm0);
            float p1 = __expf(sacc[j][1] - nm0);
            float p2 = __expf(sacc[j][2] - nm1);
            float p3 = __expf(sacc[j][3] - nm1);
            rs0 += p0 + p1; rs1 += p2 + p3;
            *(uint2*)&Ps[r * QP + j * 8 + 2 * q] = make_uint2(rtf(p0), rtf(p1));
            *(uint2*)&Ps[(r + 8) * QP + j * 8 + 2 * q] = make_uint2(rtf(p2), rtf(p3));
        }
        rs0 += __shfl_xor_sync(0xffffffffu, rs0, 1);
        rs0 += __shfl_xor_sync(0xffffffffu, rs0, 2);
        rs1 += __shfl_xor_sync(0xffffffffu, rs1, 1);
        rs1 += __shfl_xor_sync(0xffffffffu, rs1, 2);
        l0 = l0 * al0 + rs0;
        l1 = l1 * al1 + rs1;
#pragma unroll
        for (int j = 0; j < 8; j++) {
            oacc[j][0] *= al0; oacc[j][1] *= al0;
            oacc[j][2] *= al1; oacc[j][3] *= al1;
        }
        __syncwarp();   // own-warp Ps writes -> own-warp frag reads

        // ---- O += P @ V  (m16 x n64, k=64) ----
#pragma unroll
        for (int ks = 0; ks < 8; ks++) {
            int k0 = ks * 8;
            uint32_t a[4];
            a[0] = __float_as_uint(Ps[r * QP + k0 + q]);
            a[1] = __float_as_uint(Ps[(r + 8) * QP + k0 + q]);
            a[2] = __float_as_uint(Ps[r * QP + k0 + q + 4]);
            a[3] = __float_as_uint(Ps[(r + 8) * QP + k0 + q + 4]);
#pragma unroll
            for (int j = 0; j < 8; j++) {
                uint32_t b0 = __float_as_uint(Vs[(k0 + q) * VP + j * 8 + g]);
                uint32_t b1 = __float_as_uint(Vs[(k0 + q + 4) * VP + j * 8 + g]);
                mma_tf32(oacc[j], a, b0, b1);
            }
        }
    }

    // normalize + write ctx in [B,S,H,D] layout
    float inv0 = 1.f / l0, inv1 = 1.f / l1;
#pragma unroll
    for (int j = 0; j < 8; j++) {
        int col = j * 8 + 2 * q;
        *(float2*)&O[base + (size_t)(q0 + r) * E_ + col] =
            make_float2(oacc[j][0] * inv0, oacc[j][1] * inv0);
        *(float2*)&O[base + (size_t)(q0 + r + 8) * E_ + col] =
            make_float2(oacc[j][2] * inv1, oacc[j][3] * inv1);
    }
}

// ---------------------------------------------------------------------------
extern "C" void kernel_launch(void* const* d_in, const int* in_sizes, int n_in,
                              void* d_out, int out_size)
{
    const float* X  = (const float*)d_in[0];
    const float* Wq = (const float*)d_in[1];
    const float* Wk = (const float*)d_in[2];
    const float* Wv = (const float*)d_in[3];
    const float* Wo = (const float*)d_in[4];
    const float* bo = (const float*)d_in[5];
    float* out = (float*)d_out;

    float *Qp, *Kp, *Vp, *Cp;
    cudaGetSymbolAddress((void**)&Qp, g_Q);
    cudaGetSymbolAddress((void**)&Kp, g_K);
    cudaGetSymbolAddress((void**)&Vp, g_V);
    cudaGetSymbolAddress((void**)&Cp, g_Ctx);

    int gemm_smem = GEMM_SMEM_FLOATS * (int)sizeof(float);   // 61440
    cudaFuncSetAttribute(gemm_tf32_nt,
                         cudaFuncAttributeMaxDynamicSharedMemorySize, gemm_smem);
    int flash_smem = FLASH_SMEM_FLOATS * (int)sizeof(float); // 105472
    cudaFuncSetAttribute(flash_tf32_kernel,
                         cudaFuncAttributeMaxDynamicSharedMemorySize, flash_smem);

    dim3 gemm_grid(E_ / 128, MTOT / 128);   // (8, 64)
    gemm_tf32_nt<<<gemm_grid, 512, gemm_smem>>>(X, Wq, nullptr, Qp, MTOT, E_, E_);
    gemm_tf32_nt<<<gemm_grid, 512, gemm_smem>>>(X, Wk, nullptr, Kp, MTOT, E_, E_);
    gemm_tf32_nt<<<gemm_grid, 512, gemm_smem>>>(X, Wv, nullptr, Vp, MTOT, E_, E_);

    flash_tf32_kernel<<<dim3(S_ / 128, H_, B_), 256, flash_smem>>>(Qp, Kp, Vp, Cp);

    gemm_tf32_nt<<<gemm_grid, 512, gemm_smem>>>(Cp, Wo, bo, out, MTOT, E_, E_);
}

// round 10
// speedup vs baseline: 1.5029x; 1.5029x over previous
#include <cuda_runtime.h>
#include <cstdint>

#define B_ 4
#define S_ 2048
#define E_ 1024
#define H_ 16
#define D_ 64
#define MTOT (B_*S_)   // 8192

// Scratch (device globals: allocation-free rule)
__device__ float g_Q[B_*S_*E_];
__device__ float g_K[B_*S_*E_];
__device__ float g_V[B_*S_*E_];
__device__ float g_Ctx[B_*S_*E_];

// ---------------------------------------------------------------------------
// helpers
// ---------------------------------------------------------------------------
// HMMA.TF32 reads the top 19 bits of an fp32 register. +0x1000 on the bit
// pattern = round-to-nearest (ties away) in 1 IADD. (== cvt.rna numerics.)
__device__ __forceinline__ uint32_t rtf(float x) {
    return __float_as_uint(x) + 0x1000u;
}

__device__ __forceinline__ void mma_tf32(float* c, const uint32_t* a,
                                         uint32_t b0, uint32_t b1) {
    asm volatile(
        "mma.sync.aligned.m16n8k8.row.col.f32.tf32.tf32.f32 "
        "{%0,%1,%2,%3}, {%4,%5,%6,%7}, {%8,%9}, {%0,%1,%2,%3};"
        : "+f"(c[0]), "+f"(c[1]), "+f"(c[2]), "+f"(c[3])
        : "r"(a[0]), "r"(a[1]), "r"(a[2]), "r"(a[3]), "r"(b0), "r"(b1));
}

__device__ __forceinline__ void cp_async16(uint32_t saddr, const void* g) {
    asm volatile("cp.async.cg.shared.global [%0], [%1], 16;"
                 :: "r"(saddr), "l"(g));
}
__device__ __forceinline__ void cp_commit() {
    asm volatile("cp.async.commit_group;");
}
template <int N>
__device__ __forceinline__ void cp_wait() {
    asm volatile("cp.async.wait_group %0;" :: "n"(N));
}

// ---------------------------------------------------------------------------
// tf32 GEMM (NT): C[m,n] = sum_k A[m,k]*B[n,k] (+ bias[n])
// CTA 128x128, BK=16, 128 thr (4 warps, 2x2), warp tile 64x64.
// Per k-half: 32 LDS feed 32 MMAs -> 1.0 LDS/MMA (vs 1.5 at 64x32).
// Staging: each thread owns one 128-row; a k-tile row is 16 floats = 64 B
// = FOUR 16B cp.async chunks per matrix (round-9 bug: only 2 were issued).
// 2 CTAs/SM (launch_bounds(128,2), 60KB smem each).
// 3-stage cp.async pipeline, one __syncthreads per k-tile.
// RN rounding at fragment load (+0x1000). smem pitch 20: conflict-free.
// ---------------------------------------------------------------------------
#define GP 20
#define GSTG (128 * GP)
#define GEMM_SMEM_FLOATS (6 * GSTG)   // As[3] + Bs[3] = 61440 B

__global__ __launch_bounds__(128, 2) void gemm_tf32_nt(
    const float* __restrict__ A, const float* __restrict__ Bm,
    const float* __restrict__ bias, float* __restrict__ C,
    int M, int N, int K)
{
    extern __shared__ float smg[];
    float* As = smg;             // 3 buffers of GSTG
    float* Bs = smg + 3 * GSTG;

    const int tid = threadIdx.x;
    const int warp = tid >> 5, lane = tid & 31;
    const int g = lane >> 2, q = lane & 3;
    const int wm = warp >> 1;          // 0..1 (64-row slabs)
    const int wn = warp & 1;           // 0..1 (64-col slabs)
    const int bm = blockIdx.y, bn = blockIdx.x;

    const float* Ap = A + (size_t)(bm * 128 + tid) * K;
    const float* Bp = Bm + (size_t)(bn * 128 + tid) * K;

    uint32_t sA0 = (uint32_t)__cvta_generic_to_shared(&As[tid * GP]);
    uint32_t sB0 = (uint32_t)__cvta_generic_to_shared(&Bs[tid * GP]);
    const uint32_t stg = (uint32_t)(GSTG * sizeof(float));

    float acc[4][8][4];
#pragma unroll
    for (int i = 0; i < 4; i++)
#pragma unroll
        for (int j = 0; j < 8; j++)
#pragma unroll
            for (int t = 0; t < 4; t++) acc[i][j][t] = 0.f;

    const int nt = K / 16;
    // prologue: stage tiles 0 and 1 into bufs 0 and 1 (full 16 floats each)
#pragma unroll
    for (int p = 0; p < 2; p++) {
#pragma unroll
        for (int c = 0; c < 4; c++) {
            cp_async16(sA0 + p * stg + c * 16, Ap + p * 16 + c * 4);
            cp_async16(sB0 + p * stg + c * 16, Bp + p * 16 + c * 4);
        }
        cp_commit();
    }

    for (int kt = 0; kt < nt; kt++) {
        const int cur = kt % 3;
        cp_wait<1>();          // tile kt resident
        __syncthreads();       // also: readers of buf (kt+2)%3 (from kt-1) done
        if (kt + 2 < nt) {
            const int nxt = (kt + 2) % 3;
#pragma unroll
            for (int c = 0; c < 4; c++) {
                cp_async16(sA0 + nxt * stg + c * 16, Ap + (kt + 2) * 16 + c * 4);
                cp_async16(sB0 + nxt * stg + c * 16, Bp + (kt + 2) * 16 + c * 4);
            }
            cp_commit();
        } else {
            cp_commit();       // empty group keeps count in step for cp_wait<1>
        }

        const float* as = As + cur * GSTG;
        const float* bs = Bs + cur * GSTG;
#pragma unroll
        for (int kh = 0; kh < 2; kh++) {
            const int k0 = kh * 8;
            uint32_t af[4][4];
#pragma unroll
            for (int i = 0; i < 4; i++) {
                int r = wm * 64 + i * 16 + g;
                af[i][0] = rtf(as[r * GP + k0 + q]);
                af[i][1] = rtf(as[(r + 8) * GP + k0 + q]);
                af[i][2] = rtf(as[r * GP + k0 + q + 4]);
                af[i][3] = rtf(as[(r + 8) * GP + k0 + q + 4]);
            }
#pragma unroll
            for (int j = 0; j < 8; j++) {
                int n = wn * 64 + j * 8 + g;
                uint32_t bf0 = rtf(bs[n * GP + k0 + q]);
                uint32_t bf1 = rtf(bs[n * GP + k0 + q + 4]);
#pragma unroll
                for (int i = 0; i < 4; i++)
                    mma_tf32(acc[i][j], af[i], bf0, bf1);
            }
        }
    }

    // epilogue
#pragma unroll
    for (int i = 0; i < 4; i++) {
        int r0 = bm * 128 + wm * 64 + i * 16 + g;
#pragma unroll
        for (int j = 0; j < 8; j++) {
            int col = bn * 128 + wn * 64 + j * 8 + 2 * q;
            float bx = 0.f, by = 0.f;
            if (bias) { bx = bias[col]; by = bias[col + 1]; }
            float2 v0 = make_float2(acc[i][j][0] + bx, acc[i][j][1] + by);
            float2 v1 = make_float2(acc[i][j][2] + bx, acc[i][j][3] + by);
            *(float2*)&C[(size_t)r0 * N + col] = v0;
            *(float2*)&C[(size_t)(r0 + 8) * N + col] = v1;
        }
    }
}

// ---------------------------------------------------------------------------
// tf32 flash attention (round-6 config verbatim — 492us proven).
// BQ=128, BKV=64, 128 threads (4 warps), m32 warps: every K/V fragment LDS
// feeds 2 MMAs. RN rounding at smem staging.
// Pitches: Qs/Ks/Ps 68, Vs 72 (conflict-free). smem 105472 B -> 2 CTAs/SM.
// ---------------------------------------------------------------------------
#define QP 68
#define VP 72
#define FLASH_SMEM_FLOATS (128*QP + 64*QP + 64*VP + 128*QP)   // 26368

__global__ __launch_bounds__(128) void flash_tf32_kernel(
    const float* __restrict__ Q, const float* __restrict__ K,
    const float* __restrict__ V, float* __restrict__ O)
{
    extern __shared__ float sm[];
    float* Qs = sm;                    // [128][QP]
    float* Ks = Qs + 128 * QP;         // [64][QP]
    float* Vs = Ks + 64 * QP;          // [64][VP]
    float* Ps = Vs + 64 * VP;          // [128][QP]

    const int tid = threadIdx.x;
    const int warp = tid >> 5, lane = tid & 31;
    const int g = lane >> 2, q = lane & 3;
    const int b = blockIdx.z, h = blockIdx.y;
    const int q0 = blockIdx.x * 128;
    const int base = b * S_ * E_ + h * D_;
    const int r0 = warp * 32 + g;
    const int r1 = r0 + 16;

#pragma unroll
    for (int t = 0; t < 16; t++) {
        int u = tid + t * 128;
        int rr = u >> 4, cc = (u & 15) * 4;
        float4 v = *(const float4*)&Q[base + (size_t)(q0 + rr) * E_ + cc];
        uint4 o;
        o.x = rtf(v.x * 0.125f); o.y = rtf(v.y * 0.125f);
        o.z = rtf(v.z * 0.125f); o.w = rtf(v.w * 0.125f);
        *(uint4*)&Qs[rr * QP + cc] = o;
    }

    float m0a = -1e30f, m0b = -1e30f, m1a = -1e30f, m1b = -1e30f;
    float l0a = 0.f, l0b = 0.f, l1a = 0.f, l1b = 0.f;
    float oacc0[8][4], oacc1[8][4];
#pragma unroll
    for (int j = 0; j < 8; j++)
#pragma unroll
        for (int t = 0; t < 4; t++) { oacc0[j][t] = 0.f; oacc1[j][t] = 0.f; }

    for (int t0 = 0; t0 < S_; t0 += 64) {
        __syncthreads();
#pragma unroll
        for (int t = 0; t < 8; t++) {
            int u = tid + t * 128;
            int rr = u >> 4, cc = (u & 15) * 4;
            float4 kv = *(const float4*)&K[base + (size_t)(t0 + rr) * E_ + cc];
            float4 vv = *(const float4*)&V[base + (size_t)(t0 + rr) * E_ + cc];
            uint4 ko, vo;
            ko.x = rtf(kv.x); ko.y = rtf(kv.y); ko.z = rtf(kv.z); ko.w = rtf(kv.w);
            vo.x = rtf(vv.x); vo.y = rtf(vv.y); vo.z = rtf(vv.z); vo.w = rtf(vv.w);
            *(uint4*)&Ks[rr * QP + cc] = ko;
            *(uint4*)&Vs[rr * VP + cc] = vo;
        }
        __syncthreads();

        float s0[8][4], s1[8][4];
#pragma unroll
        for (int j = 0; j < 8; j++)
#pragma unroll
            for (int t = 0; t < 4; t++) { s0[j][t] = 0.f; s1[j][t] = 0.f; }

#pragma unroll
        for (int ks = 0; ks < 8; ks++) {
            int k0 = ks * 8;
            uint32_t a0[4], a1[4];
            a0[0] = __float_as_uint(Qs[r0 * QP + k0 + q]);
            a0[1] = __float_as_uint(Qs[(r0 + 8) * QP + k0 + q]);
            a0[2] = __float_as_uint(Qs[r0 * QP + k0 + q + 4]);
            a0[3] = __float_as_uint(Qs[(r0 + 8) * QP + k0 + q + 4]);
            a1[0] = __float_as_uint(Qs[r1 * QP + k0 + q]);
            a1[1] = __float_as_uint(Qs[(r1 + 8) * QP + k0 + q]);
            a1[2] = __float_as_uint(Qs[r1 * QP + k0 + q + 4]);
            a1[3] = __float_as_uint(Qs[(r1 + 8) * QP + k0 + q + 4]);
#pragma unroll
            for (int j = 0; j < 8; j++) {
                int n = j * 8 + g;
                uint32_t b0 = __float_as_uint(Ks[n * QP + k0 + q]);
                uint32_t b1 = __float_as_uint(Ks[n * QP + k0 + q + 4]);
                mma_tf32(s0[j], a0, b0, b1);
                mma_tf32(s1[j], a1, b0, b1);
            }
        }

        {
            float mxa = -1e30f, mxb = -1e30f;
#pragma unroll
            for (int j = 0; j < 8; j++) {
                mxa = fmaxf(mxa, fmaxf(s0[j][0], s0[j][1]));
                mxb = fmaxf(mxb, fmaxf(s0[j][2], s0[j][3]));
            }
            mxa = fmaxf(mxa, __shfl_xor_sync(0xffffffffu, mxa, 1));
            mxa = fmaxf(mxa, __shfl_xor_sync(0xffffffffu, mxa, 2));
            mxb = fmaxf(mxb, __shfl_xor_sync(0xffffffffu, mxb, 1));
            mxb = fmaxf(mxb, __shfl_xor_sync(0xffffffffu, mxb, 2));
            float nma = fmaxf(m0a, mxa), nmb = fmaxf(m0b, mxb);
            float ala = __expf(m0a - nma), alb = __expf(m0b - nmb);
            m0a = nma; m0b = nmb;
            float rsa = 0.f, rsb = 0.f;
#pragma unroll
            for (int j = 0; j < 8; j++) {
                float p0 = __expf(s0[j][0] - nma);
                float p1 = __expf(s0[j][1] - nma);
                float p2 = __expf(s0[j][2] - nmb);
                float p3 = __expf(s0[j][3] - nmb);
                rsa += p0 + p1; rsb += p2 + p3;
                *(uint2*)&Ps[r0 * QP + j * 8 + 2 * q] = make_uint2(rtf(p0), rtf(p1));
                *(uint2*)&Ps[(r0 + 8) * QP + j * 8 + 2 * q] = make_uint2(rtf(p2), rtf(p3));
            }
            rsa += __shfl_xor_sync(0xffffffffu, rsa, 1);
            rsa += __shfl_xor_sync(0xffffffffu, rsa, 2);
            rsb += __shfl_xor_sync(0xffffffffu, rsb, 1);
            rsb += __shfl_xor_sync(0xffffffffu, rsb, 2);
            l0a = l0a * ala + rsa;
            l0b = l0b * alb + rsb;
#pragma unroll
            for (int j = 0; j < 8; j++) {
                oacc0[j][0] *= ala; oacc0[j][1] *= ala;
                oacc0[j][2] *= alb; oacc0[j][3] *= alb;
            }
        }
        {
            float mxa = -1e30f, mxb = -1e30f;
#pragma unroll
            for (int j = 0; j < 8; j++) {
                mxa = fmaxf(mxa, fmaxf(s1[j][0], s1[j][1]));
                mxb = fmaxf(mxb, fmaxf(s1[j][2], s1[j][3]));
            }
            mxa = fmaxf(mxa, __shfl_xor_sync(0xffffffffu, mxa, 1));
            mxa = fmaxf(mxa, __shfl_xor_sync(0xffffffffu, mxa, 2));
            mxb = fmaxf(mxb, __shfl_xor_sync(0xffffffffu, mxb, 1));
            mxb = fmaxf(mxb, __shfl_xor_sync(0xffffffffu, mxb, 2));
            float nma = fmaxf(m1a, mxa), nmb = fmaxf(m1b, mxb);
            float ala = __expf(m1a - nma), alb = __expf(m1b - nmb);
            m1a = nma; m1b = nmb;
            float rsa = 0.f, rsb = 0.f;
#pragma unroll
            for (int j = 0; j < 8; j++) {
                float p0 = __expf(s1[j][0] - nma);
                float p1 = __expf(s1[j][1] - nma);
                float p2 = __expf(s1[j][2] - nmb);
                float p3 = __expf(s1[j][3] - nmb);
                rsa += p0 + p1; rsb += p2 + p3;
                *(uint2*)&Ps[r1 * QP + j * 8 + 2 * q] = make_uint2(rtf(p0), rtf(p1));
                *(uint2*)&Ps[(r1 + 8) * QP + j * 8 + 2 * q] = make_uint2(rtf(p2), rtf(p3));
            }
            rsa += __shfl_xor_sync(0xffffffffu, rsa, 1);
            rsa += __shfl_xor_sync(0xffffffffu, rsa, 2);
            rsb += __shfl_xor_sync(0xffffffffu, rsb, 1);
            rsb += __shfl_xor_sync(0xffffffffu, rsb, 2);
            l1a = l1a * ala + rsa;
            l1b = l1b * alb + rsb;
#pragma unroll
            for (int j = 0; j < 8; j++) {
                oacc1[j][0] *= ala; oacc1[j][1] *= ala;
                oacc1[j][2] *= alb; oacc1[j][3] *= alb;
            }
        }
        __syncwarp();

#pragma unroll
        for (int ks = 0; ks < 8; ks++) {
            int k0 = ks * 8;
            uint32_t a0[4], a1[4];
            a0[0] = __float_as_uint(Ps[r0 * QP + k0 + q]);
            a0[1] = __float_as_uint(Ps[(r0 + 8) * QP + k0 + q]);
            a0[2] = __float_as_uint(Ps[r0 * QP + k0 + q + 4]);
            a0[3] = __float_as_uint(Ps[(r0 + 8) * QP + k0 + q + 4]);
            a1[0] = __float_as_uint(Ps[r1 * QP + k0 + q]);
            a1[1] = __float_as_uint(Ps[(r1 + 8) * QP + k0 + q]);
            a1[2] = __float_as_uint(Ps[r1 * QP + k0 + q + 4]);
            a1[3] = __float_as_uint(Ps[(r1 + 8) * QP + k0 + q + 4]);
#pragma unroll
            for (int j = 0; j < 8; j++) {
                uint32_t b0 = __float_as_uint(Vs[(k0 + q) * VP + j * 8 + g]);
                uint32_t b1 = __float_as_uint(Vs[(k0 + q + 4) * VP + j * 8 + g]);
                mma_tf32(oacc0[j], a0, b0, b1);
                mma_tf32(oacc1[j], a1, b0, b1);
            }
        }
    }

    float i0a = 1.f / l0a, i0b = 1.f / l0b, i1a = 1.f / l1a, i1b = 1.f / l1b;
#pragma unroll
    for (int j = 0; j < 8; j++) {
        int col = j * 8 + 2 * q;
        *(float2*)&O[base + (size_t)(q0 + r0) * E_ + col] =
            make_float2(oacc0[j][0] * i0a, oacc0[j][1] * i0a);
        *(float2*)&O[base + (size_t)(q0 + r0 + 8) * E_ + col] =
            make_float2(oacc0[j][2] * i0b, oacc0[j][3] * i0b);
        *(float2*)&O[base + (size_t)(q0 + r1) * E_ + col] =
            make_float2(oacc1[j][0] * i1a, oacc1[j][1] * i1a);
        *(float2*)&O[base + (size_t)(q0 + r1 + 8) * E_ + col] =
            make_float2(oacc1[j][2] * i1b, oacc1[j][3] * i1b);
    }
}

// ---------------------------------------------------------------------------
extern "C" void kernel_launch(void* const* d_in, const int* in_sizes, int n_in,
                              void* d_out, int out_size)
{
    const float* X  = (const float*)d_in[0];
    const float* Wq = (const float*)d_in[1];
    const float* Wk = (const float*)d_in[2];
    const float* Wv = (const float*)d_in[3];
    const float* Wo = (const float*)d_in[4];
    const float* bo = (const float*)d_in[5];
    float* out = (float*)d_out;

    float *Qp, *Kp, *Vp, *Cp;
    cudaGetSymbolAddress((void**)&Qp, g_Q);
    cudaGetSymbolAddress((void**)&Kp, g_K);
    cudaGetSymbolAddress((void**)&Vp, g_V);
    cudaGetSymbolAddress((void**)&Cp, g_Ctx);

    int gemm_smem = GEMM_SMEM_FLOATS * (int)sizeof(float);   // 61440
    cudaFuncSetAttribute(gemm_tf32_nt,
                         cudaFuncAttributeMaxDynamicSharedMemorySize, gemm_smem);
    int flash_smem = FLASH_SMEM_FLOATS * (int)sizeof(float); // 105472
    cudaFuncSetAttribute(flash_tf32_kernel,
                         cudaFuncAttributeMaxDynamicSharedMemorySize, flash_smem);

    dim3 gemm_grid(E_ / 128, MTOT / 128);   // (8, 64)
    gemm_tf32_nt<<<gemm_grid, 128, gemm_smem>>>(X, Wq, nullptr, Qp, MTOT, E_, E_);
    gemm_tf32_nt<<<gemm_grid, 128, gemm_smem>>>(X, Wk, nullptr, Kp, MTOT, E_, E_);
    gemm_tf32_nt<<<gemm_grid, 128, gemm_smem>>>(X, Wv, nullptr, Vp, MTOT, E_, E_);

    flash_tf32_kernel<<<dim3(S_ / 128, H_, B_), 128, flash_smem>>>(Qp, Kp, Vp, Cp);

    gemm_tf32_nt<<<gemm_grid, 128, gemm_smem>>>(Cp, Wo, bo, out, MTOT, E_, E_);
}